// round 8
// baseline (speedup 1.0000x reference)
#include <cuda_runtime.h>
#include <cuda_bf16.h>

// B=8, SEQ=4096, DIM=64.
// out = scale * rope(Q) @ (rope(K)^T @ rope(V))   (associativity; no softmax)
// scale = 1/sqrt(64) = 0.125

#define BATCH   8
#define SEQ     4096
#define DIM     64
#define NC      32            // chunks per batch (both k1 and k3)
#define CHUNK   128           // rows per CTA
#define SUB     32            // rows per sub-tile (4 sub-tiles, double-buffered)

__device__ float g_partials[NC * BATCH * DIM * DIM];  // 4 MB
__device__ float g_M[BATCH * DIM * DIM];              // 128 KB

typedef unsigned long long ull;

__device__ __forceinline__ ull pk2(float x) {
    ull r; asm("mov.b64 %0, {%1,%1};" : "=l"(r) : "f"(x)); return r;
}
__device__ __forceinline__ void fma2(ull& d, ull a, ull b) {
    asm("fma.rn.f32x2 %0, %1, %2, %0;" : "+l"(d) : "l"(a), "l"(b));
}
__device__ __forceinline__ float2 up2(ull v) {
    float2 r; asm("mov.b64 {%0,%1}, %2;" : "=f"(r.x), "=f"(r.y) : "l"(v)); return r;
}
__device__ __forceinline__ float4 rope4(float4 x, float4 f) {
    float4 o;
    o.x = x.x * f.x - x.y * f.y;  o.y = x.x * f.y + x.y * f.x;
    o.z = x.z * f.z - x.w * f.w;  o.w = x.z * f.w + x.w * f.z;
    return o;
}

// ---------------------------------------------------------------------------
// Kernel 1: partial M = sum over 128 rows of rope(k) ⊗ rope(v).
// 256 threads; thread (ti=t>>4, tj=t&15) owns a 4x4 tile of the 64x64 M.
// Software pipeline: prefetch sub-tile t+1 into regs, GEMM sub-tile t from
// smem (double-buffered), then rope+store t+1. One sync per sub-tile.
// ---------------------------------------------------------------------------
__global__ __launch_bounds__(256) void kv_outer_kernel(
    const float* __restrict__ K, const float* __restrict__ V,
    const float* __restrict__ FK, const float* __restrict__ FV)
{
    const int b = blockIdx.y;
    const int c = blockIdx.x;
    const int t = threadIdx.x;

    __shared__ float sk[2][SUB * DIM];   // 8 KB each
    __shared__ float sv[2][SUB * DIM];

    const float4* K4  = (const float4*)(K  + ((size_t)b * SEQ + (size_t)c * CHUNK) * DIM);
    const float4* V4  = (const float4*)(V  + ((size_t)b * SEQ + (size_t)c * CHUNK) * DIM);
    const float4* FK4 = (const float4*)(FK + (size_t)c * CHUNK * DIM);
    const float4* FV4 = (const float4*)(FV + (size_t)c * CHUNK * DIM);

    float4 kr[2], vr[2], fkr[2], fvr[2];

    // prologue: load + rope + store sub-tile 0
#pragma unroll
    for (int u = 0; u < 2; u++) {
        const int f = t + 256 * u;
        kr[u] = K4[f]; vr[u] = V4[f]; fkr[u] = FK4[f]; fvr[u] = FV4[f];
    }
#pragma unroll
    for (int u = 0; u < 2; u++) {
        const int f = t + 256 * u;
        const int r = f >> 4, c4 = f & 15;
        *(float4*)&sk[0][r * DIM + 4 * c4] = rope4(kr[u], fkr[u]);
        *(float4*)&sv[0][r * DIM + 4 * c4] = rope4(vr[u], fvr[u]);
    }
    __syncthreads();

    const int ti = t >> 4;
    const int tj = t & 15;
    const int i0 = 4 * ti;
    const int j0 = 4 * tj;

    ull acc[4][2];
#pragma unroll
    for (int i = 0; i < 4; i++) { acc[i][0] = 0ULL; acc[i][1] = 0ULL; }

#pragma unroll
    for (int tile = 0; tile < 4; tile++) {
        // prefetch next sub-tile (LDGs issued before the GEMM hides latency)
        if (tile < 3) {
            const int off = (tile + 1) * (SUB * DIM / 4);
#pragma unroll
            for (int u = 0; u < 2; u++) {
                const int f = off + t + 256 * u;
                kr[u] = K4[f]; vr[u] = V4[f]; fkr[u] = FK4[f]; fvr[u] = FV4[f];
            }
        }

        const float* skb = sk[tile & 1];
        const float* svb = sv[tile & 1];
#pragma unroll 8
        for (int r = 0; r < SUB; r++) {
            const float4 kk = *(const float4*)&skb[r * DIM + i0];
            const ull* vp = (const ull*)&svb[r * DIM + j0];
            const ull v0 = vp[0], v1 = vp[1];
            const ull k0 = pk2(kk.x), k1 = pk2(kk.y);
            const ull k2 = pk2(kk.z), k3 = pk2(kk.w);
            fma2(acc[0][0], k0, v0); fma2(acc[0][1], k0, v1);
            fma2(acc[1][0], k1, v0); fma2(acc[1][1], k1, v1);
            fma2(acc[2][0], k2, v0); fma2(acc[2][1], k2, v1);
            fma2(acc[3][0], k3, v0); fma2(acc[3][1], k3, v1);
        }

        if (tile < 3) {
            const int bb = (tile + 1) & 1;
#pragma unroll
            for (int u = 0; u < 2; u++) {
                const int f = t + 256 * u;
                const int r = f >> 4, c4 = f & 15;
                *(float4*)&sk[bb][r * DIM + 4 * c4] = rope4(kr[u], fkr[u]);
                *(float4*)&sv[bb][r * DIM + 4 * c4] = rope4(vr[u], fvr[u]);
            }
            __syncthreads();
        }
    }

    float* P = &g_partials[((size_t)c * BATCH + b) * (DIM * DIM)];
#pragma unroll
    for (int i = 0; i < 4; i++) {
        const float2 a0 = up2(acc[i][0]);
        const float2 a1 = up2(acc[i][1]);
        *(float4*)&P[(i0 + i) * DIM + j0] = make_float4(a0.x, a0.y, a1.x, a1.y);
    }
}

// ---------------------------------------------------------------------------
// Kernel 2: reduce NC partials -> g_M.  32 blocks x 256 threads,
// one float4 output per thread (8192 total), NC=32 loads each.
// ---------------------------------------------------------------------------
__global__ __launch_bounds__(256) void reduce_kernel()
{
    const int idx = blockIdx.x * 256 + threadIdx.x;   // 0..8191 (float4)
    const float4* P = (const float4*)g_partials;
    float4 s0 = make_float4(0.f, 0.f, 0.f, 0.f);
    float4 s1 = make_float4(0.f, 0.f, 0.f, 0.f);
    float4 s2 = make_float4(0.f, 0.f, 0.f, 0.f);
    float4 s3 = make_float4(0.f, 0.f, 0.f, 0.f);
#pragma unroll 8
    for (int c = 0; c < NC; c += 4) {
        const float4 a = P[(size_t)(c + 0) * 8192 + idx];
        const float4 b = P[(size_t)(c + 1) * 8192 + idx];
        const float4 d = P[(size_t)(c + 2) * 8192 + idx];
        const float4 e = P[(size_t)(c + 3) * 8192 + idx];
        s0.x += a.x; s0.y += a.y; s0.z += a.z; s0.w += a.w;
        s1.x += b.x; s1.y += b.y; s1.z += b.z; s1.w += b.w;
        s2.x += d.x; s2.y += d.y; s2.z += d.z; s2.w += d.w;
        s3.x += e.x; s3.y += e.y; s3.z += e.z; s3.w += e.w;
    }
    ((float4*)g_M)[idx] = make_float4(s0.x + s1.x + s2.x + s3.x,
                                      s0.y + s1.y + s2.y + s3.y,
                                      s0.z + s1.z + s2.z + s3.z,
                                      s0.w + s1.w + s2.w + s3.w);
}

// ---------------------------------------------------------------------------
// Kernel 3: out = scale * rope(Q) @ M[b].  Same pipeline as k1.
// 256 threads; per sub-tile, thread (ti=t>>3: row, tj=t&7: cols 8tj..8tj+7).
// q staged row-major stride 72 (16B-aligned; banks (8ti+d)%32 distinct).
// ---------------------------------------------------------------------------
#define QSTR 72

__global__ __launch_bounds__(256) void qm_kernel(
    const float* __restrict__ Q, const float* __restrict__ FQ,
    float* __restrict__ OUT)
{
    const int b  = blockIdx.y;
    const int rc = blockIdx.x;
    const int t  = threadIdx.x;

    __shared__ float sM[DIM * DIM];        // 16 KB plain
    __shared__ float sq[2][SUB * QSTR];    // 9 KB each

    // load M[b]: 1024 float4, 4 per thread
    {
        const float4* Ms = (const float4*)&g_M[(size_t)b * DIM * DIM];
        float4* Md = (float4*)sM;
#pragma unroll
        for (int u = 0; u < 4; u++) Md[t + 256 * u] = Ms[t + 256 * u];
    }

    const size_t gbase = ((size_t)b * SEQ + (size_t)rc * CHUNK) * DIM;
    const float4* Q4 = (const float4*)(Q + gbase);
    const float4* F4 = (const float4*)(FQ + (size_t)rc * CHUNK * DIM);

    float4 qr[2], fr[2];

    // prologue: sub-tile 0
#pragma unroll
    for (int u = 0; u < 2; u++) {
        const int f = t + 256 * u;
        qr[u] = Q4[f]; fr[u] = F4[f];
    }
#pragma unroll
    for (int u = 0; u < 2; u++) {
        const int f = t + 256 * u;
        const int r = f >> 4, c4 = f & 15;
        *(float4*)&sq[0][r * QSTR + 4 * c4] = rope4(qr[u], fr[u]);
    }
    __syncthreads();

    const int ti = t >> 3;   // row within sub-tile (0..31)
    const int tj = t & 7;    // cols 8tj..8tj+7
    const float scale = 0.125f;
    float* O = OUT + gbase;

#pragma unroll
    for (int tile = 0; tile < 4; tile++) {
        if (tile < 3) {
            const int off = (tile + 1) * (SUB * DIM / 4);
#pragma unroll
            for (int u = 0; u < 2; u++) {
                const int f = off + t + 256 * u;
                qr[u] = Q4[f]; fr[u] = F4[f];
            }
        }

        const float* qrow = &sq[tile & 1][ti * QSTR];
        ull acc[4];
        acc[0] = acc[1] = acc[2] = acc[3] = 0ULL;
#pragma unroll 8
        for (int d = 0; d < DIM; d += 2) {
            const float2 q2 = *(const float2*)&qrow[d];
            const ull q0 = pk2(q2.x), q1 = pk2(q2.y);
            const ull* m0 = (const ull*)&sM[d * DIM + 8 * tj];
            const ull* m1 = (const ull*)&sM[(d + 1) * DIM + 8 * tj];
            fma2(acc[0], q0, m0[0]); fma2(acc[1], q0, m0[1]);
            fma2(acc[2], q0, m0[2]); fma2(acc[3], q0, m0[3]);
            fma2(acc[0], q1, m1[0]); fma2(acc[1], q1, m1[1]);
            fma2(acc[2], q1, m1[2]); fma2(acc[3], q1, m1[3]);
        }

        // write output row
        {
            const int row = tile * SUB + ti;
            const float2 a0 = up2(acc[0]), a1 = up2(acc[1]);
            const float2 a2 = up2(acc[2]), a3 = up2(acc[3]);
            *(float4*)&O[(size_t)row * DIM + 8 * tj] =
                make_float4(a0.x * scale, a0.y * scale, a1.x * scale, a1.y * scale);
            *(float4*)&O[(size_t)row * DIM + 8 * tj + 4] =
                make_float4(a2.x * scale, a2.y * scale, a3.x * scale, a3.y * scale);
        }

        if (tile < 3) {
            const int bb = (tile + 1) & 1;
#pragma unroll
            for (int u = 0; u < 2; u++) {
                const int f = t + 256 * u;
                const int r = f >> 4, c4 = f & 15;
                *(float4*)&sq[bb][r * QSTR + 4 * c4] = rope4(qr[u], fr[u]);
            }
            __syncthreads();
        }
    }
}

// ---------------------------------------------------------------------------
extern "C" void kernel_launch(void* const* d_in, const int* in_sizes, int n_in,
                              void* d_out, int out_size)
{
    const float* q  = (const float*)d_in[0];
    const float* k  = (const float*)d_in[1];
    const float* v  = (const float*)d_in[2];
    const float* fq = (const float*)d_in[3];
    const float* fk = (const float*)d_in[4];
    const float* fv = (const float*)d_in[5];
    float* out = (float*)d_out;

    kv_outer_kernel<<<dim3(NC, BATCH), 256>>>(k, v, fk, fv);
    reduce_kernel<<<32, 256>>>();
    qm_kernel<<<dim3(NC, BATCH), 256>>>(q, fq, out);
}

// round 9
// speedup vs baseline: 1.9823x; 1.9823x over previous
#include <cuda_runtime.h>
#include <cuda_bf16.h>
#include <cstdint>

// B=8, SEQ=4096, DIM=64.
// out = scale * rope(Q) @ (rope(K)^T @ rope(V))   (associativity; no softmax)
// scale = 1/sqrt(64) = 0.125
// Tensor-core path: mma.sync.m16n8k8 TF32 with 2-way operand split (3 MMAs)
// for fp32-class accuracy.

#define BATCH  8
#define SEQ    4096
#define DIM    64
#define NC     16          // 256-row chunks per batch
#define CH     256         // rows per CTA
#define SROWS  32          // rows per stage
#define NSTG   (CH / SROWS)

__device__ float g_partials[NC * BATCH * DIM * DIM];  // 2 MB
__device__ float g_M[BATCH * DIM * DIM];              // 128 KB

// ---------------------------------------------------------------------------
__device__ __forceinline__ uint32_t f2tf32(float x) {
    uint32_t r; asm("cvt.rna.tf32.f32 %0, %1;" : "=r"(r) : "f"(x)); return r;
}
__device__ __forceinline__ float4 rope4(float4 x, float4 f) {
    float4 o;
    o.x = x.x * f.x - x.y * f.y;  o.y = x.x * f.y + x.y * f.x;
    o.z = x.z * f.z - x.w * f.w;  o.w = x.z * f.w + x.w * f.z;
    return o;
}
// D(16x8) += A(16x8,row) * B(8x8,col); tf32 operands, f32 accumulate.
__device__ __forceinline__ void mma8(float* c, const uint32_t* a, const uint32_t* b) {
    asm volatile(
        "mma.sync.aligned.m16n8k8.row.col.f32.tf32.tf32.f32 "
        "{%0,%1,%2,%3}, {%4,%5,%6,%7}, {%8,%9}, {%0,%1,%2,%3};\n"
        : "+f"(c[0]), "+f"(c[1]), "+f"(c[2]), "+f"(c[3])
        : "r"(a[0]), "r"(a[1]), "r"(a[2]), "r"(a[3]), "r"(b[0]), "r"(b[1]));
}
// split x into (hi tf32-rounded bits, lo = x - hi as raw f32 bits)
__device__ __forceinline__ void split1(float x, uint32_t& hi, uint32_t& lo) {
    hi = f2tf32(x);
    lo = __float_as_uint(x - __uint_as_float(hi));
}

// ---------------------------------------------------------------------------
// Kernel 1: partial M = rope(K)^T @ rope(V) over a 256-row chunk.
// 8 warps: m-tile (w&3, 16 rows of M each) x k-half (w>>2, 16 seq rows/stage).
// smem: sk = rope'd K rows (raw fp32), svh/svl = rope'd V pre-split.
// Fragment LDS maps: word%32 = 8*tig + g (+const) -> full bank permutation.
// ---------------------------------------------------------------------------
__global__ __launch_bounds__(256) void kv_outer_kernel(
    const float* __restrict__ K, const float* __restrict__ V,
    const float* __restrict__ FK, const float* __restrict__ FV)
{
    const int b = blockIdx.y;
    const int c = blockIdx.x;
    const int t = threadIdx.x;
    const int w = t >> 5;
    const int lane = t & 31;
    const int g = lane >> 2;      // 0..7
    const int tig = lane & 3;     // 0..3

    __shared__ float smem[3 * SROWS * 72];   // 27.6 KB
    float* sk  = smem;                        // [r][d] stride 72
    float* svh = smem + SROWS * 72;
    float* svl = smem + 2 * SROWS * 72;

    const float4* K4  = (const float4*)(K + (size_t)b * SEQ * DIM);
    const float4* V4  = (const float4*)(V + (size_t)b * SEQ * DIM);
    const float4* FK4 = (const float4*)FK;
    const float4* FV4 = (const float4*)FV;

    const int m0 = 16 * (w & 3);
    const int kh = w >> 2;

    float acc[8][4];
#pragma unroll
    for (int j = 0; j < 8; j++)
#pragma unroll
        for (int p = 0; p < 4; p++) acc[j][p] = 0.0f;

#pragma unroll 1
    for (int s = 0; s < NSTG; s++) {
        if (s) __syncthreads();   // prev stage fully consumed
        // ---- stage 32 rows: rope K (raw), rope+split V ----
#pragma unroll
        for (int u = 0; u < 2; u++) {
            const int f  = t + 256 * u;       // 0..511
            const int r  = f >> 4;
            const int c4 = f & 15;
            const int gi = (c * CH + s * SROWS + r) * 16 + c4;
            *(float4*)&sk[r * 72 + 4 * c4] = rope4(K4[gi], FK4[gi]);
            const float4 vv = rope4(V4[gi], FV4[gi]);
            uint32_t h0, l0, h1, l1, h2, l2, h3, l3;
            split1(vv.x, h0, l0); split1(vv.y, h1, l1);
            split1(vv.z, h2, l2); split1(vv.w, h3, l3);
            float4 vh = make_float4(__uint_as_float(h0), __uint_as_float(h1),
                                    __uint_as_float(h2), __uint_as_float(h3));
            float4 vl = make_float4(__uint_as_float(l0), __uint_as_float(l1),
                                    __uint_as_float(l2), __uint_as_float(l3));
            *(float4*)&svh[r * 72 + 4 * c4] = vh;
            *(float4*)&svl[r * 72 + 4 * c4] = vl;
        }
        __syncthreads();

        // ---- MMA: 2 k-steps of 8 seq rows ----
#pragma unroll
        for (int ks = 0; ks < 2; ks++) {
            const int krow = kh * 16 + ks * 8;
            // A = K^T: a(mrow, kcol) -> sk[seq=krow+kcol][dim=m0+mrow]
            uint32_t ah[4], al[4];
            {
                const float a0 = sk[(krow + tig)     * 72 + m0 + g];
                const float a1 = sk[(krow + tig)     * 72 + m0 + g + 8];
                const float a2 = sk[(krow + tig + 4) * 72 + m0 + g];
                const float a3 = sk[(krow + tig + 4) * 72 + m0 + g + 8];
                split1(a0, ah[0], al[0]); split1(a1, ah[1], al[1]);
                split1(a2, ah[2], al[2]); split1(a3, ah[3], al[3]);
            }
#pragma unroll
            for (int j = 0; j < 8; j++) {
                const int n0 = 8 * j;
                uint32_t bh[2], bl[2];
                bh[0] = __float_as_uint(svh[(krow + tig)     * 72 + n0 + g]);
                bh[1] = __float_as_uint(svh[(krow + tig + 4) * 72 + n0 + g]);
                bl[0] = __float_as_uint(svl[(krow + tig)     * 72 + n0 + g]);
                bl[1] = __float_as_uint(svl[(krow + tig + 4) * 72 + n0 + g]);
                mma8(acc[j], ah, bh);
                mma8(acc[j], ah, bl);
                mma8(acc[j], al, bh);
            }
        }
    }

    // ---- combine k-halves through smem, warps 0-3 write the partial ----
    __syncthreads();
    float* comb = smem;   // 64 x 68 = 4352 floats (fits in 3*2304)
    if (w >= 4) {
#pragma unroll
        for (int j = 0; j < 8; j++) {
            const int col = 8 * j + 2 * tig;
            *(float2*)&comb[(m0 + g)     * 68 + col] = make_float2(acc[j][0], acc[j][1]);
            *(float2*)&comb[(m0 + g + 8) * 68 + col] = make_float2(acc[j][2], acc[j][3]);
        }
    }
    __syncthreads();
    if (w < 4) {
        float* P = g_partials + ((size_t)c * BATCH + b) * (DIM * DIM);
#pragma unroll
        for (int j = 0; j < 8; j++) {
            const int col = 8 * j + 2 * tig;
            const float2 u0 = *(const float2*)&comb[(m0 + g)     * 68 + col];
            const float2 u1 = *(const float2*)&comb[(m0 + g + 8) * 68 + col];
            *(float2*)&P[(m0 + g)     * DIM + col] =
                make_float2(acc[j][0] + u0.x, acc[j][1] + u0.y);
            *(float2*)&P[(m0 + g + 8) * DIM + col] =
                make_float2(acc[j][2] + u1.x, acc[j][3] + u1.y);
        }
    }
}

// ---------------------------------------------------------------------------
// Kernel 2: reduce NC=16 partials -> g_M (8192 float4 outputs)
// ---------------------------------------------------------------------------
__global__ __launch_bounds__(256) void reduce_kernel()
{
    const int idx = blockIdx.x * 256 + threadIdx.x;   // float4 index, 0..8191
    const float4* P = (const float4*)g_partials;
    float4 s0 = make_float4(0.f, 0.f, 0.f, 0.f);
    float4 s1 = make_float4(0.f, 0.f, 0.f, 0.f);
#pragma unroll
    for (int c = 0; c < NC; c += 2) {
        const float4 a = P[(size_t)(c + 0) * 8192 + idx];
        const float4 b = P[(size_t)(c + 1) * 8192 + idx];
        s0.x += a.x; s0.y += a.y; s0.z += a.z; s0.w += a.w;
        s1.x += b.x; s1.y += b.y; s1.z += b.z; s1.w += b.w;
    }
    ((float4*)g_M)[idx] = make_float4(s0.x + s1.x, s0.y + s1.y,
                                      s0.z + s1.z, s0.w + s1.w);
}

// ---------------------------------------------------------------------------
// Kernel 3: out = scale * rope(Q) @ M[b].
// 8 warps: m-tile (w&1: 16 of 32 staged rows) x n-quarter (w>>1: 2 n-tiles).
// M pre-split hi/lo in smem (stride 72); Q staged raw (stride 68), split at
// fragment load. No k-split -> direct coalesced STG of the output.
// ---------------------------------------------------------------------------
__global__ __launch_bounds__(256) void qm_kernel(
    const float* __restrict__ Q, const float* __restrict__ FQ,
    float* __restrict__ OUT)
{
    const int b  = blockIdx.y;
    const int rc = blockIdx.x;
    const int t  = threadIdx.x;
    const int w  = t >> 5;
    const int lane = t & 31;
    const int g = lane >> 2;
    const int tig = lane & 3;

    __shared__ float smem[2 * DIM * 72 + SROWS * 68];  // 45.6 KB
    float* sMh = smem;                 // [k][n] stride 72
    float* sMl = smem + DIM * 72;
    float* sq  = smem + 2 * DIM * 72;  // [row][d] stride 68

    // ---- load + split M[b] (1024 float4, 4 per thread) ----
    {
        const float4* M4 = (const float4*)(g_M + (size_t)b * DIM * DIM);
#pragma unroll
        for (int u = 0; u < 4; u++) {
            const int f  = t + 256 * u;
            const int k  = f >> 4;
            const int n0 = 4 * (f & 15);
            const float4 m = M4[f];
            uint32_t h0, l0, h1, l1, h2, l2, h3, l3;
            split1(m.x, h0, l0); split1(m.y, h1, l1);
            split1(m.z, h2, l2); split1(m.w, h3, l3);
            *(float4*)&sMh[k * 72 + n0] =
                make_float4(__uint_as_float(h0), __uint_as_float(h1),
                            __uint_as_float(h2), __uint_as_float(h3));
            *(float4*)&sMl[k * 72 + n0] =
                make_float4(__uint_as_float(l0), __uint_as_float(l1),
                            __uint_as_float(l2), __uint_as_float(l3));
        }
    }

    const float4* Q4  = (const float4*)(Q + (size_t)b * SEQ * DIM);
    const float4* FQ4 = (const float4*)FQ;
    const int m0s = 16 * (w & 1);
    const int nq  = w >> 1;           // 0..3
    const float scale = 0.125f;       // 1/sqrt(64)

#pragma unroll 1
    for (int s = 0; s < NSTG; s++) {
        if (s) __syncthreads();       // prev stage's sq fully consumed
        const int R = rc * CH + s * SROWS;
        // ---- stage 32 rope'd Q rows ----
#pragma unroll
        for (int u = 0; u < 2; u++) {
            const int f  = t + 256 * u;
            const int r  = f >> 4;
            const int c4 = f & 15;
            const int gi = (R + r) * 16 + c4;
            *(float4*)&sq[r * 68 + 4 * c4] = rope4(Q4[gi], FQ4[gi]);
        }
        __syncthreads();   // also covers the one-time M staging at s=0

        float cc[2][4];
#pragma unroll
        for (int jj = 0; jj < 2; jj++)
#pragma unroll
            for (int p = 0; p < 4; p++) cc[jj][p] = 0.0f;

#pragma unroll
        for (int ks = 0; ks < 8; ks++) {
            const int k0 = 8 * ks;
            // A = Qr: a(mrow, kcol) -> sq[row=m0s+mrow][d=k0+kcol]
            uint32_t ah[4], al[4];
            {
                const float a0 = sq[(m0s + g)     * 68 + k0 + tig];
                const float a1 = sq[(m0s + g + 8) * 68 + k0 + tig];
                const float a2 = sq[(m0s + g)     * 68 + k0 + tig + 4];
                const float a3 = sq[(m0s + g + 8) * 68 + k0 + tig + 4];
                split1(a0, ah[0], al[0]); split1(a1, ah[1], al[1]);
                split1(a2, ah[2], al[2]); split1(a3, ah[3], al[3]);
            }
#pragma unroll
            for (int jj = 0; jj < 2; jj++) {
                const int n0 = 8 * (2 * nq + jj);
                uint32_t bh[2], bl[2];
                bh[0] = __float_as_uint(sMh[(k0 + tig)     * 72 + n0 + g]);
                bh[1] = __float_as_uint(sMh[(k0 + tig + 4) * 72 + n0 + g]);
                bl[0] = __float_as_uint(sMl[(k0 + tig)     * 72 + n0 + g]);
                bl[1] = __float_as_uint(sMl[(k0 + tig + 4) * 72 + n0 + g]);
                mma8(cc[jj], ah, bh);
                mma8(cc[jj], ah, bl);
                mma8(cc[jj], al, bh);
            }
        }

        // ---- write 16 output rows for this warp's tiles ----
        float* O = OUT + ((size_t)b * SEQ + R) * DIM;
#pragma unroll
        for (int jj = 0; jj < 2; jj++) {
            const int col = 8 * (2 * nq + jj) + 2 * tig;
            *(float2*)&O[(size_t)(m0s + g)     * DIM + col] =
                make_float2(cc[jj][0] * scale, cc[jj][1] * scale);
            *(float2*)&O[(size_t)(m0s + g + 8) * DIM + col] =
                make_float2(cc[jj][2] * scale, cc[jj][3] * scale);
        }
    }
}

// ---------------------------------------------------------------------------
extern "C" void kernel_launch(void* const* d_in, const int* in_sizes, int n_in,
                              void* d_out, int out_size)
{
    const float* q  = (const float*)d_in[0];
    const float* k  = (const float*)d_in[1];
    const float* v  = (const float*)d_in[2];
    const float* fq = (const float*)d_in[3];
    const float* fk = (const float*)d_in[4];
    const float* fv = (const float*)d_in[5];
    float* out = (float*)d_out;

    kv_outer_kernel<<<dim3(NC, BATCH), 256>>>(k, v, fk, fv);
    reduce_kernel<<<32, 256>>>();
    qm_kernel<<<dim3(NC, BATCH), 256>>>(q, fq, out);
}